// round 11
// baseline (speedup 1.0000x reference)
#include <cuda_runtime.h>
#include <math.h>
#include <stdint.h>

// StableMoEGate v6 (re-bench; R10 was an infra failure, kernel never ran):
// mma.sync.m16n8k8 TF32, 2-way split (3 passes),
// chunk-distance A prefetch (16 scalars/chunk) + cp.async B double-buffer.
// logits = x @ W^T (T=16384, H=4096, E=64); softmax; top-2; renorm softmax.
// Output: single f32 buffer [2T scores][2T idx-as-float][1 aux=0].

#define Hdim 4096
#define Edim 64
#define MT   64                  // tokens per CTA
#define NCHUNK 64                // chunks per K-group (1024 k / 16)
#define SMEM_BYTES 65536         // 2 buf x 4 g x 2 k8 x 2 spl x 64 n x 32B

__device__ float g_wsplit[2 * 64 * 4096];   // [spl][n][k8(512)][8 perm]

static __device__ __forceinline__ uint32_t smem_u32(const void* p) {
    uint32_t a;
    asm("{ .reg .u64 t; cvta.to.shared.u64 t, %1; cvt.u32.u64 %0, t; }" : "=r"(a) : "l"(p));
    return a;
}
static __device__ __forceinline__ uint32_t f2tf32(float f) {
    uint32_t u;
    asm("cvt.rna.tf32.f32 %0, %1;" : "=r"(u) : "f"(f));
    return u;
}

__global__ void __launch_bounds__(256) split_w_kernel(const float* __restrict__ W) {
    const int i = blockIdx.x * 256 + threadIdx.x;
    if (i < 64 * 4096) {
        const int n = i >> 12, k = i & 4095;
        const float w = W[(size_t)n * 4096 + k];
        const uint32_t hi = f2tf32(w);
        const float hif = __uint_as_float(hi);
        const uint32_t lo = f2tf32(w - hif);
        const int k8i = k >> 3, kin = k & 7;
        const int pos = (kin & 3) * 2 + (kin >> 2);        // (k,k+4) adjacent
        const int dst = n * 4096 + k8i * 8 + pos;
        g_wsplit[dst]          = hif;
        g_wsplit[262144 + dst] = __uint_as_float(lo);
    }
}

#define MMA(d, a0, a1, a2, a3, b0, b1)                                           \
    asm volatile("mma.sync.aligned.m16n8k8.row.col.f32.tf32.tf32.f32 "           \
                 "{%0,%1,%2,%3}, {%4,%5,%6,%7}, {%8,%9}, {%0,%1,%2,%3};"         \
                 : "+f"(d[0]), "+f"(d[1]), "+f"(d[2]), "+f"(d[3])                \
                 : "r"(a0), "r"(a1), "r"(a2), "r"(a3), "r"(b0), "r"(b1))

__global__ void __launch_bounds__(256, 2) moe_gate_v6_kernel(
    const float* __restrict__ x,
    float* __restrict__ out,
    int T)
{
    extern __shared__ float smem[];
    const uint32_t sbase = smem_u32(smem);

    const int tid  = threadIdx.x;
    const int lid  = tid & 31;
    const int wid  = tid >> 5;
    const int g    = wid >> 1;             // K-group 0..3 : k in [g*1024, +1024)
    const int tokg = wid & 1;              // token half
    const int gid  = lid >> 2;             // 0..7
    const int tid4 = lid & 3;              // 0..3
    const int m0   = blockIdx.x * MT;

    // ---- cp.async B: 8 x 16B per thread per chunk ----
    uint32_t dstoff[8], woff[8];
    #pragma unroll
    for (int j = 0; j < 8; j++) {
        const int id   = j * 256 + tid;
        const int half = id & 1;
        const int n    = (id >> 1) & 63;
        const int spl  = (id >> 7) & 1;
        const int k8   = (id >> 8) & 1;
        const int gg   = (id >> 9) & 3;
        dstoff[j] = (uint32_t)(((((gg * 2 + k8) * 2 + spl) * 64 + n) * 32) + half * 16);
        woff[j]   = (uint32_t)((spl * 262144 + n * 4096 + (gg * 128 + k8) * 8 + half * 4) * 4);
    }
    const char* wbase = (const char*)g_wsplit;

    // ---- A fragment byte offsets (chunk 0, k8 0) ----
    uint32_t aoff[8];
    #pragma unroll
    for (int m = 0; m < 2; m++) {
        const int r = m0 + tokg * 32 + m * 16 + gid;
        const int c = g * 1024 + tid4;
        aoff[m * 4 + 0] = (uint32_t)(((size_t)r * Hdim + c) * 4);
        aoff[m * 4 + 1] = (uint32_t)(((size_t)(r + 8) * Hdim + c) * 4);
        aoff[m * 4 + 2] = (uint32_t)(((size_t)r * Hdim + c + 4) * 4);
        aoff[m * 4 + 3] = (uint32_t)(((size_t)(r + 8) * Hdim + c + 4) * 4);
    }
    const char* xb = (const char*)x;

    float acc[2][8][4];
    #pragma unroll
    for (int m = 0; m < 2; m++)
        #pragma unroll
        for (int nt = 0; nt < 8; nt++)
            #pragma unroll
            for (int q = 0; q < 4; q++) acc[m][nt][q] = 0.0f;

    auto issueB = [&](int c) {
        const uint32_t buf = (uint32_t)(c & 1);
        #pragma unroll
        for (int j = 0; j < 8; j++)
            asm volatile("cp.async.cg.shared.global [%0], [%1], 16;"
                         :: "r"(sbase + buf * 32768u + dstoff[j]),
                            "l"(wbase + woff[j] + (uint32_t)c * 64u));
        asm volatile("cp.async.commit_group;" ::: "memory");
    };

    // A chunk registers: [k8*8 + frag]; chunk stride 64B, k8 stride 32B
    float ar[16], an[16];
    #pragma unroll
    for (int k8 = 0; k8 < 2; k8++)
        #pragma unroll
        for (int i = 0; i < 8; i++)
            ar[k8 * 8 + i] = *(const float*)(xb + aoff[i] + k8 * 32);

    issueB(0);

    for (int c = 0; c < NCHUNK; c++) {
        asm volatile("cp.async.wait_group 0;" ::: "memory");
        __syncthreads();
        if (c + 1 < NCHUNK) issueB(c + 1);

        // prefetch NEXT chunk's 16 A scalars (full-chunk latency distance)
        const uint32_t cn = (uint32_t)((c + 1 < NCHUNK ? c + 1 : c) * 64);
        #pragma unroll
        for (int k8 = 0; k8 < 2; k8++)
            #pragma unroll
            for (int i = 0; i < 8; i++)
                an[k8 * 8 + i] = *(const float*)(xb + aoff[i] + cn + k8 * 32);

        #pragma unroll
        for (int k8 = 0; k8 < 2; k8++) {
            uint32_t ahi[8], alo[8];
            #pragma unroll
            for (int i = 0; i < 8; i++) {
                const float v = ar[k8 * 8 + i];
                ahi[i] = f2tf32(v);
                alo[i] = f2tf32(v - __uint_as_float(ahi[i]));
            }

            const uint32_t b0a = sbase + (uint32_t)((c & 1) * 32768)
                               + (uint32_t)(((g * 2 + k8) * 2) * 2048)
                               + (uint32_t)(gid * 32 + tid4 * 8);
            #pragma unroll
            for (int nt = 0; nt < 8; nt++) {
                uint32_t bh0, bh1, bl0, bl1;
                asm volatile("ld.shared.v2.b32 {%0,%1},[%2];"
                             : "=r"(bh0), "=r"(bh1) : "r"(b0a + (uint32_t)(nt * 256)));
                asm volatile("ld.shared.v2.b32 {%0,%1},[%2];"
                             : "=r"(bl0), "=r"(bl1) : "r"(b0a + (uint32_t)(nt * 256) + 2048u));
                #pragma unroll
                for (int m = 0; m < 2; m++) {
                    MMA(acc[m][nt], ahi[m*4+0], ahi[m*4+1], ahi[m*4+2], ahi[m*4+3], bh0, bh1);
                    MMA(acc[m][nt], ahi[m*4+0], ahi[m*4+1], ahi[m*4+2], ahi[m*4+3], bl0, bl1);
                    MMA(acc[m][nt], alo[m*4+0], alo[m*4+1], alo[m*4+2], alo[m*4+3], bh0, bh1);
                }
            }
        }
        #pragma unroll
        for (int i = 0; i < 16; i++) ar[i] = an[i];
    }
    __syncthreads();

    // ---- split-K reduction into logits smem [64][68] ----
    #pragma unroll
    for (int gg = 0; gg < 4; gg++) {
        if (g == gg) {
            #pragma unroll
            for (int m = 0; m < 2; m++) {
                const int r = tokg * 32 + m * 16 + gid;
                #pragma unroll
                for (int nt = 0; nt < 8; nt++) {
                    const int col = nt * 8 + tid4 * 2;
                    if (gg == 0) {
                        smem[r * 68 + col]           = acc[m][nt][0];
                        smem[r * 68 + col + 1]       = acc[m][nt][1];
                        smem[(r + 8) * 68 + col]     = acc[m][nt][2];
                        smem[(r + 8) * 68 + col + 1] = acc[m][nt][3];
                    } else {
                        smem[r * 68 + col]           += acc[m][nt][0];
                        smem[r * 68 + col + 1]       += acc[m][nt][1];
                        smem[(r + 8) * 68 + col]     += acc[m][nt][2];
                        smem[(r + 8) * 68 + col + 1] += acc[m][nt][3];
                    }
                }
            }
        }
        __syncthreads();
    }

    if (tid < MT) {
        const float* row = smem + tid * 68;
        float best1 = -3.4e38f, best2 = -3.4e38f;
        int i1 = 0, i2 = 0;
        #pragma unroll 8
        for (int e = 0; e < Edim; e++) {
            const float l = row[e];
            if (l > best1) { best2 = best1; i2 = i1; best1 = l; i1 = e; }
            else if (l > best2) { best2 = l; i2 = e; }
        }
        float Z = 0.0f;
        #pragma unroll 8
        for (int e = 0; e < Edim; e++) Z += expf(row[e] - best1);
        const float s1 = 1.0f / Z;
        const float s2 = expf(best2 - best1) / Z;
        const float p1 = 1.0f / (1.0f + expf(s2 - s1));
        const float p2 = 1.0f - p1;

        const int m = m0 + tid;
        out[2 * m + 0] = p1;
        out[2 * m + 1] = p2;
        float* oi = out + 2 * T;              // indices stored as float values
        oi[2 * m + 0] = (float)i1;
        oi[2 * m + 1] = (float)i2;
    }
    if (blockIdx.x == 0 && tid == 0) out[4 * T] = 0.0f;
}

extern "C" void kernel_launch(void* const* d_in, const int* in_sizes, int n_in,
                              void* d_out, int out_size)
{
    const float* x = (const float*)d_in[0];
    const float* W = (const float*)d_in[1];
    int T = in_sizes[0] / Hdim;   // 16384
    (void)n_in; (void)out_size;

    static bool attr_done = false;
    if (!attr_done) {
        cudaFuncSetAttribute(moe_gate_v6_kernel,
                             cudaFuncAttributeMaxDynamicSharedMemorySize, SMEM_BYTES);
        attr_done = true;
    }
    split_w_kernel<<<1024, 256>>>(W);
    moe_gate_v6_kernel<<<T / MT, 256, SMEM_BYTES>>>(x, (float*)d_out, T);
}

// round 12
// speedup vs baseline: 1.0074x; 1.0074x over previous
#include <cuda_runtime.h>
#include <math.h>
#include <stdint.h>

// StableMoEGate v7: mma.sync.m16n8k8 TF32, 2-way split (3 passes),
// NON-VOLATILE MMAs + pairwise-nt pass-major interleave to kill acc RAW stalls.
// logits = x @ W^T (T=16384, H=4096, E=64); softmax; top-2; renorm softmax.
// Output: single f32 buffer [2T scores][2T idx-as-float][1 aux=0].

#define Hdim 4096
#define Edim 64
#define MT   64                  // tokens per CTA
#define NCHUNK 64                // chunks per K-group (1024 k / 16)
#define SMEM_BYTES 65536         // 2 buf x 4 g x 2 k8 x 2 spl x 64 n x 32B

__device__ float g_wsplit[2 * 64 * 4096];   // [spl][n][k8(512)][8 perm]

static __device__ __forceinline__ uint32_t smem_u32(const void* p) {
    uint32_t a;
    asm("{ .reg .u64 t; cvta.to.shared.u64 t, %1; cvt.u32.u64 %0, t; }" : "=r"(a) : "l"(p));
    return a;
}
static __device__ __forceinline__ uint32_t f2tf32(float f) {
    uint32_t u;
    asm("cvt.rna.tf32.f32 %0, %1;" : "=r"(u) : "f"(f));
    return u;
}

__global__ void __launch_bounds__(256) split_w_kernel(const float* __restrict__ W) {
    const int i = blockIdx.x * 256 + threadIdx.x;
    if (i < 64 * 4096) {
        const int n = i >> 12, k = i & 4095;
        const float w = W[(size_t)n * 4096 + k];
        const uint32_t hi = f2tf32(w);
        const float hif = __uint_as_float(hi);
        const uint32_t lo = f2tf32(w - hif);
        const int k8i = k >> 3, kin = k & 7;
        const int pos = (kin & 3) * 2 + (kin >> 2);        // (k,k+4) adjacent
        const int dst = n * 4096 + k8i * 8 + pos;
        g_wsplit[dst]          = hif;
        g_wsplit[262144 + dst] = __uint_as_float(lo);
    }
}

// NON-volatile: pure register op; lets ptxas reschedule across chains.
#define MMA_NV(d, a0, a1, a2, a3, b0, b1)                                        \
    asm("mma.sync.aligned.m16n8k8.row.col.f32.tf32.tf32.f32 "                    \
        "{%0,%1,%2,%3}, {%4,%5,%6,%7}, {%8,%9}, {%0,%1,%2,%3};"                  \
        : "+f"(d[0]), "+f"(d[1]), "+f"(d[2]), "+f"(d[3])                         \
        : "r"(a0), "r"(a1), "r"(a2), "r"(a3), "r"(b0), "r"(b1))

__global__ void __launch_bounds__(256, 2) moe_gate_v7_kernel(
    const float* __restrict__ x,
    float* __restrict__ out,
    int T)
{
    extern __shared__ float smem[];
    const uint32_t sbase = smem_u32(smem);

    const int tid  = threadIdx.x;
    const int lid  = tid & 31;
    const int wid  = tid >> 5;
    const int g    = wid >> 1;             // K-group 0..3 : k in [g*1024, +1024)
    const int tokg = wid & 1;              // token half
    const int gid  = lid >> 2;             // 0..7
    const int tid4 = lid & 3;              // 0..3
    const int m0   = blockIdx.x * MT;

    // ---- cp.async B: 8 x 16B per thread per chunk ----
    uint32_t dstoff[8], woff[8];
    #pragma unroll
    for (int j = 0; j < 8; j++) {
        const int id   = j * 256 + tid;
        const int half = id & 1;
        const int n    = (id >> 1) & 63;
        const int spl  = (id >> 7) & 1;
        const int k8   = (id >> 8) & 1;
        const int gg   = (id >> 9) & 3;
        dstoff[j] = (uint32_t)(((((gg * 2 + k8) * 2 + spl) * 64 + n) * 32) + half * 16);
        woff[j]   = (uint32_t)((spl * 262144 + n * 4096 + (gg * 128 + k8) * 8 + half * 4) * 4);
    }
    const char* wbase = (const char*)g_wsplit;

    // ---- A fragment byte offsets (chunk 0, k8 0) ----
    uint32_t aoff[8];
    #pragma unroll
    for (int m = 0; m < 2; m++) {
        const int r = m0 + tokg * 32 + m * 16 + gid;
        const int c = g * 1024 + tid4;
        aoff[m * 4 + 0] = (uint32_t)(((size_t)r * Hdim + c) * 4);
        aoff[m * 4 + 1] = (uint32_t)(((size_t)(r + 8) * Hdim + c) * 4);
        aoff[m * 4 + 2] = (uint32_t)(((size_t)r * Hdim + c + 4) * 4);
        aoff[m * 4 + 3] = (uint32_t)(((size_t)(r + 8) * Hdim + c + 4) * 4);
    }
    const char* xb = (const char*)x;

    float acc0[8][4], acc1[8][4];          // m=0 / m=1 accumulators
    #pragma unroll
    for (int nt = 0; nt < 8; nt++)
        #pragma unroll
        for (int q = 0; q < 4; q++) { acc0[nt][q] = 0.0f; acc1[nt][q] = 0.0f; }

    auto issueB = [&](int c) {
        const uint32_t buf = (uint32_t)(c & 1);
        #pragma unroll
        for (int j = 0; j < 8; j++)
            asm volatile("cp.async.cg.shared.global [%0], [%1], 16;"
                         :: "r"(sbase + buf * 32768u + dstoff[j]),
                            "l"(wbase + woff[j] + (uint32_t)c * 64u));
        asm volatile("cp.async.commit_group;" ::: "memory");
    };

    // A chunk registers: [k8*8 + frag]
    float ar[16], an[16];
    #pragma unroll
    for (int k8 = 0; k8 < 2; k8++)
        #pragma unroll
        for (int i = 0; i < 8; i++)
            ar[k8 * 8 + i] = *(const float*)(xb + aoff[i] + k8 * 32);

    issueB(0);

    for (int c = 0; c < NCHUNK; c++) {
        asm volatile("cp.async.wait_group 0;" ::: "memory");
        __syncthreads();
        if (c + 1 < NCHUNK) issueB(c + 1);

        const uint32_t cn = (uint32_t)((c + 1 < NCHUNK ? c + 1 : c) * 64);
        #pragma unroll
        for (int k8 = 0; k8 < 2; k8++)
            #pragma unroll
            for (int i = 0; i < 8; i++)
                an[k8 * 8 + i] = *(const float*)(xb + aoff[i] + cn + k8 * 32);

        #pragma unroll
        for (int k8 = 0; k8 < 2; k8++) {
            uint32_t ahi[8], alo[8];
            #pragma unroll
            for (int i = 0; i < 8; i++) {
                const float v = ar[k8 * 8 + i];
                ahi[i] = f2tf32(v);
                alo[i] = f2tf32(v - __uint_as_float(ahi[i]));
            }

            const uint32_t b0a = sbase + (uint32_t)((c & 1) * 32768)
                               + (uint32_t)(((g * 2 + k8) * 2) * 2048)
                               + (uint32_t)(gid * 32 + tid4 * 8);

            // pairwise-nt, pass-major: 12 MMAs cycling 4 independent acc chains
            #pragma unroll
            for (int nt = 0; nt < 8; nt += 2) {
                uint32_t bh0a, bh1a, bl0a, bl1a, bh0b, bh1b, bl0b, bl1b;
                asm volatile("ld.shared.v2.b32 {%0,%1},[%2];"
                             : "=r"(bh0a), "=r"(bh1a) : "r"(b0a + (uint32_t)(nt * 256)));
                asm volatile("ld.shared.v2.b32 {%0,%1},[%2];"
                             : "=r"(bl0a), "=r"(bl1a) : "r"(b0a + (uint32_t)(nt * 256) + 2048u));
                asm volatile("ld.shared.v2.b32 {%0,%1},[%2];"
                             : "=r"(bh0b), "=r"(bh1b) : "r"(b0a + (uint32_t)((nt + 1) * 256)));
                asm volatile("ld.shared.v2.b32 {%0,%1},[%2];"
                             : "=r"(bl0b), "=r"(bl1b) : "r"(b0a + (uint32_t)((nt + 1) * 256) + 2048u));

                // pass hh
                MMA_NV(acc0[nt],     ahi[0], ahi[1], ahi[2], ahi[3], bh0a, bh1a);
                MMA_NV(acc1[nt],     ahi[4], ahi[5], ahi[6], ahi[7], bh0a, bh1a);
                MMA_NV(acc0[nt + 1], ahi[0], ahi[1], ahi[2], ahi[3], bh0b, bh1b);
                MMA_NV(acc1[nt + 1], ahi[4], ahi[5], ahi[6], ahi[7], bh0b, bh1b);
                // pass hl
                MMA_NV(acc0[nt],     ahi[0], ahi[1], ahi[2], ahi[3], bl0a, bl1a);
                MMA_NV(acc1[nt],     ahi[4], ahi[5], ahi[6], ahi[7], bl0a, bl1a);
                MMA_NV(acc0[nt + 1], ahi[0], ahi[1], ahi[2], ahi[3], bl0b, bl1b);
                MMA_NV(acc1[nt + 1], ahi[4], ahi[5], ahi[6], ahi[7], bl0b, bl1b);
                // pass lh
                MMA_NV(acc0[nt],     alo[0], alo[1], alo[2], alo[3], bh0a, bh1a);
                MMA_NV(acc1[nt],     alo[4], alo[5], alo[6], alo[7], bh0a, bh1a);
                MMA_NV(acc0[nt + 1], alo[0], alo[1], alo[2], alo[3], bh0b, bh1b);
                MMA_NV(acc1[nt + 1], alo[4], alo[5], alo[6], alo[7], bh0b, bh1b);
            }
        }
        #pragma unroll
        for (int i = 0; i < 16; i++) ar[i] = an[i];
    }
    __syncthreads();

    // ---- split-K reduction into logits smem [64][68] ----
    #pragma unroll
    for (int gg = 0; gg < 4; gg++) {
        if (g == gg) {
            #pragma unroll
            for (int m = 0; m < 2; m++) {
                const int r = tokg * 32 + m * 16 + gid;
                #pragma unroll
                for (int nt = 0; nt < 8; nt++) {
                    const float* a4 = (m == 0) ? acc0[nt] : acc1[nt];
                    const int col = nt * 8 + tid4 * 2;
                    if (gg == 0) {
                        smem[r * 68 + col]           = a4[0];
                        smem[r * 68 + col + 1]       = a4[1];
                        smem[(r + 8) * 68 + col]     = a4[2];
                        smem[(r + 8) * 68 + col + 1] = a4[3];
                    } else {
                        smem[r * 68 + col]           += a4[0];
                        smem[r * 68 + col + 1]       += a4[1];
                        smem[(r + 8) * 68 + col]     += a4[2];
                        smem[(r + 8) * 68 + col + 1] += a4[3];
                    }
                }
            }
        }
        __syncthreads();
    }

    if (tid < MT) {
        const float* row = smem + tid * 68;
        float best1 = -3.4e38f, best2 = -3.4e38f;
        int i1 = 0, i2 = 0;
        #pragma unroll 8
        for (int e = 0; e < Edim; e++) {
            const float l = row[e];
            if (l > best1) { best2 = best1; i2 = i1; best1 = l; i1 = e; }
            else if (l > best2) { best2 = l; i2 = e; }
        }
        float Z = 0.0f;
        #pragma unroll 8
        for (int e = 0; e < Edim; e++) Z += expf(row[e] - best1);
        const float s1 = 1.0f / Z;
        const float s2 = expf(best2 - best1) / Z;
        const float p1 = 1.0f / (1.0f + expf(s2 - s1));
        const float p2 = 1.0f - p1;

        const int m = m0 + tid;
        out[2 * m + 0] = p1;
        out[2 * m + 1] = p2;
        float* oi = out + 2 * T;              // indices stored as float values
        oi[2 * m + 0] = (float)i1;
        oi[2 * m + 1] = (float)i2;
    }
    if (blockIdx.x == 0 && tid == 0) out[4 * T] = 0.0f;
}

extern "C" void kernel_launch(void* const* d_in, const int* in_sizes, int n_in,
                              void* d_out, int out_size)
{
    const float* x = (const float*)d_in[0];
    const float* W = (const float*)d_in[1];
    int T = in_sizes[0] / Hdim;   // 16384
    (void)n_in; (void)out_size;

    static bool attr_done = false;
    if (!attr_done) {
        cudaFuncSetAttribute(moe_gate_v7_kernel,
                             cudaFuncAttributeMaxDynamicSharedMemorySize, SMEM_BYTES);
        attr_done = true;
    }
    split_w_kernel<<<1024, 256>>>(W);
    moe_gate_v7_kernel<<<T / MT, 256, SMEM_BYTES>>>(x, (float*)d_out, T);
}

// round 13
// speedup vs baseline: 2.1620x; 2.1461x over previous
#include <cuda_runtime.h>
#include <cuda_fp16.h>
#include <math.h>
#include <stdint.h>

// StableMoEGate v8: mma.sync.m16n8k16 FP16 with 2-way split (3 passes: hh,hl,lh).
// Half the MMA instructions, half the B LDS, half the barriers vs tf32 k8.
// logits = x @ W^T (T=16384, H=4096, E=64); softmax; top-2; renorm softmax.
// Output: single f32 buffer [2T scores][2T idx-as-float][1 aux=0].
//
// CTA 256 thr = 8 warps = 4 K-groups x 2 token-halves; warp = 32 tok x 64 exp
// over its K/4 range. Chunk = 32 k (2 k16 steps), 32 chunks, cp.async B double-buffer.

#define Hdim 4096
#define Edim 64
#define MT   64
#define NCHUNK 32
#define SMEM_BYTES 65536        // 2 buf x 32KB; chunk = 4g x 2step x 2spl x 64n x 32B

// [spl][g:4][step:64][n:64][quad:4][b01:2][kbit:2] fp16
__device__ __half g_wsplit[2 * 64 * 4096];

static __device__ __forceinline__ uint32_t smem_u32(const void* p) {
    uint32_t a;
    asm("{ .reg .u64 t; cvta.to.shared.u64 t, %1; cvt.u32.u64 %0, t; }" : "=r"(a) : "l"(p));
    return a;
}
static __device__ __forceinline__ uint32_t h2u(__half2 h) {
    return *reinterpret_cast<uint32_t*>(&h);
}

__global__ void __launch_bounds__(256) split_w_kernel(const float* __restrict__ W) {
    const int i = blockIdx.x * 256 + threadIdx.x;
    if (i < 64 * 4096) {
        const int n = i >> 12, k = i & 4095;
        const float w = W[(size_t)n * 4096 + k];
        const __half hi = __float2half_rn(w);
        const __half lo = __float2half_rn(w - __half2float(hi));
        const int g = k >> 10, st = (k >> 4) & 63, kin = k & 15;
        const int half = kin >> 3, quad = (kin & 7) >> 1, bit = kin & 1;
        const int idx = ((g * 64 + st) * 64 + n) * 16 + quad * 4 + half * 2 + bit;
        g_wsplit[idx]           = hi;
        g_wsplit[262144 + idx]  = lo;
    }
}

// fp16 m16n8k16, f32 accumulate (non-volatile: pure register op)
#define MMAH(d, a0, a1, a2, a3, b0, b1)                                          \
    asm("mma.sync.aligned.m16n8k16.row.col.f32.f16.f16.f32 "                     \
        "{%0,%1,%2,%3}, {%4,%5,%6,%7}, {%8,%9}, {%0,%1,%2,%3};"                  \
        : "+f"(d[0]), "+f"(d[1]), "+f"(d[2]), "+f"(d[3])                         \
        : "r"(a0), "r"(a1), "r"(a2), "r"(a3), "r"(b0), "r"(b1))

__global__ void __launch_bounds__(256, 2) moe_gate_v8_kernel(
    const float* __restrict__ x,
    float* __restrict__ out,
    int T)
{
    extern __shared__ float smem[];
    const uint32_t sbase = smem_u32(smem);

    const int tid  = threadIdx.x;
    const int lid  = tid & 31;
    const int wid  = tid >> 5;
    const int g    = wid >> 1;            // K-group 0..3 : k in [g*1024, +1024)
    const int tokg = wid & 1;             // token half
    const int gid  = lid >> 2;            // 0..7
    const int tid4 = lid & 3;             // 0..3
    const int m0   = blockIdx.x * MT;

    // ---- cp.async B: 8 x 16B per thread per chunk; dst = id*16, id=j*256+tid ----
    // id bits: [gg:2][s:1][spl:1][n:6][half16:1]
    uint32_t woff[8];                     // byte offsets into g_wsplit
    #pragma unroll
    for (int j = 0; j < 8; j++) {
        const int id     = j * 256 + tid;
        const int half16 = id & 1;
        const int n      = (id >> 1) & 63;
        const int spl    = (id >> 7) & 1;
        const int s      = (id >> 8) & 1;
        const int gg     = (id >> 9) & 3;
        woff[j] = (uint32_t)((spl * 262144 + ((gg * 64 + s) * 64 + n) * 16 + half16 * 8) * 2);
    }
    const char* wbase = (const char*)g_wsplit;

    // ---- A float2 byte offsets (chunk 0, step 0) ----
    uint32_t aoff[8];
    #pragma unroll
    for (int m = 0; m < 2; m++) {
        const int r = m0 + tokg * 32 + m * 16 + gid;
        const int c = g * 1024 + tid4 * 2;
        aoff[m * 4 + 0] = (uint32_t)(((size_t)r * Hdim + c) * 4);
        aoff[m * 4 + 1] = (uint32_t)(((size_t)(r + 8) * Hdim + c) * 4);
        aoff[m * 4 + 2] = (uint32_t)(((size_t)r * Hdim + c + 8) * 4);
        aoff[m * 4 + 3] = (uint32_t)(((size_t)(r + 8) * Hdim + c + 8) * 4);
    }
    const char* xb = (const char*)x;

    float acc0[8][4], acc1[8][4];
    #pragma unroll
    for (int nt = 0; nt < 8; nt++)
        #pragma unroll
        for (int q = 0; q < 4; q++) { acc0[nt][q] = 0.0f; acc1[nt][q] = 0.0f; }

    auto issueB = [&](int c) {
        const uint32_t dbase = sbase + (uint32_t)(c & 1) * 32768u + (uint32_t)tid * 16u;
        #pragma unroll
        for (int j = 0; j < 8; j++)
            asm volatile("cp.async.cg.shared.global [%0], [%1], 16;"
                         :: "r"(dbase + (uint32_t)(j * 4096)),
                            "l"(wbase + woff[j] + (uint32_t)c * 4096u));
        asm volatile("cp.async.commit_group;" ::: "memory");
    };

    issueB(0);

    for (int c = 0; c < NCHUNK; c++) {
        asm volatile("cp.async.wait_group 0;" ::: "memory");
        __syncthreads();
        if (c + 1 < NCHUNK) issueB(c + 1);

        #pragma unroll
        for (int s = 0; s < 2; s++) {
            // load + split A: 8 float2 -> ahi/alo fragments [m][4]
            const uint32_t ka = (uint32_t)((c * 32 + s * 16) * 4);
            uint32_t ahi[8], alo[8];
            #pragma unroll
            for (int i = 0; i < 8; i++) {
                const float2 v = *(const float2*)(xb + aoff[i] + ka);
                const __half2 h = __float22half2_rn(v);
                const float2 f = __half22float2(h);
                ahi[i] = h2u(h);
                alo[i] = h2u(__floats2half2_rn(v.x - f.x, v.y - f.y));
            }

            const uint32_t b0a = sbase + (uint32_t)((c & 1) * 32768)
                               + (uint32_t)(((g * 2 + s) * 2) * 2048)
                               + (uint32_t)(gid * 32 + tid4 * 8);
            #pragma unroll
            for (int nt = 0; nt < 8; nt++) {
                uint32_t bh0, bh1, bl0, bl1;
                asm volatile("ld.shared.v2.b32 {%0,%1},[%2];"
                             : "=r"(bh0), "=r"(bh1) : "r"(b0a + (uint32_t)(nt * 256)));
                asm volatile("ld.shared.v2.b32 {%0,%1},[%2];"
                             : "=r"(bl0), "=r"(bl1) : "r"(b0a + (uint32_t)(nt * 256) + 2048u));
                MMAH(acc0[nt], ahi[0], ahi[1], ahi[2], ahi[3], bh0, bh1);
                MMAH(acc1[nt], ahi[4], ahi[5], ahi[6], ahi[7], bh0, bh1);
                MMAH(acc0[nt], ahi[0], ahi[1], ahi[2], ahi[3], bl0, bl1);
                MMAH(acc1[nt], ahi[4], ahi[5], ahi[6], ahi[7], bl0, bl1);
                MMAH(acc0[nt], alo[0], alo[1], alo[2], alo[3], bh0, bh1);
                MMAH(acc1[nt], alo[4], alo[5], alo[6], alo[7], bh0, bh1);
            }
        }
    }
    __syncthreads();

    // ---- split-K reduction into logits smem [64][68] ----
    #pragma unroll
    for (int gg = 0; gg < 4; gg++) {
        if (g == gg) {
            #pragma unroll
            for (int m = 0; m < 2; m++) {
                const int r = tokg * 32 + m * 16 + gid;
                #pragma unroll
                for (int nt = 0; nt < 8; nt++) {
                    const float* a4 = (m == 0) ? acc0[nt] : acc1[nt];
                    const int col = nt * 8 + tid4 * 2;
                    if (gg == 0) {
                        smem[r * 68 + col]           = a4[0];
                        smem[r * 68 + col + 1]       = a4[1];
                        smem[(r + 8) * 68 + col]     = a4[2];
                        smem[(r + 8) * 68 + col + 1] = a4[3];
                    } else {
                        smem[r * 68 + col]           += a4[0];
                        smem[r * 68 + col + 1]       += a4[1];
                        smem[(r + 8) * 68 + col]     += a4[2];
                        smem[(r + 8) * 68 + col + 1] += a4[3];
                    }
                }
            }
        }
        __syncthreads();
    }

    if (tid < MT) {
        const float* row = smem + tid * 68;
        float best1 = -3.4e38f, best2 = -3.4e38f;
        int i1 = 0, i2 = 0;
        #pragma unroll 8
        for (int e = 0; e < Edim; e++) {
            const float l = row[e];
            if (l > best1) { best2 = best1; i2 = i1; best1 = l; i1 = e; }
            else if (l > best2) { best2 = l; i2 = e; }
        }
        float Z = 0.0f;
        #pragma unroll 8
        for (int e = 0; e < Edim; e++) Z += expf(row[e] - best1);
        const float s1 = 1.0f / Z;
        const float s2 = expf(best2 - best1) / Z;
        const float p1 = 1.0f / (1.0f + expf(s2 - s1));
        const float p2 = 1.0f - p1;

        const int m = m0 + tid;
        out[2 * m + 0] = p1;
        out[2 * m + 1] = p2;
        float* oi = out + 2 * T;              // indices stored as float values
        oi[2 * m + 0] = (float)i1;
        oi[2 * m + 1] = (float)i2;
    }
    if (blockIdx.x == 0 && tid == 0) out[4 * T] = 0.0f;
}

extern "C" void kernel_launch(void* const* d_in, const int* in_sizes, int n_in,
                              void* d_out, int out_size)
{
    const float* x = (const float*)d_in[0];
    const float* W = (const float*)d_in[1];
    int T = in_sizes[0] / Hdim;   // 16384
    (void)n_in; (void)out_size;

    static bool attr_done = false;
    if (!attr_done) {
        cudaFuncSetAttribute(moe_gate_v8_kernel,
                             cudaFuncAttributeMaxDynamicSharedMemorySize, SMEM_BYTES);
        attr_done = true;
    }
    split_w_kernel<<<1024, 256>>>(W);
    moe_gate_v8_kernel<<<T / MT, 256, SMEM_BYTES>>>(x, (float*)d_out, T);
}